// round 16
// baseline (speedup 1.0000x reference)
#include <cuda_runtime.h>
#include <cuda_bf16.h>
#include <cstdint>

// ---------------------------------------------------------------------------
// TransducerPrediction: embed lookup + 2-layer LSTM (Keras gate order i,f,g,o)
// B=64, T=512, EMBED=512, UNITS=1024, 4U=4096.
//
// Graph (6 nodes):
//   1) gemm_tf32: xz0 = embed[tokens] @ W0 + b0
//   2) zero_cnt
//   3) lstm_rec : layer-0 recurrence -> g_h0
//   4) gemm_tf32: xz1 = g_h0 @ W1 + b1
//   5) zero_cnt
//   6) lstm_rec : layer-1 recurrence -> d_out
//
// R16 change vs R13: lstm_rec h-path reads A-fragments DIRECTLY from L2 via
// ld.global.cg (L1-bypassing) instead of cp.async smem staging. k-warps are
// remapped contiguous (warp kw owns h cols [kw*128,(kw+1)*128)) so each warp
// depends on exactly ONE producer group and polls only that counter (lane 0
// + __syncwarp). Eliminates 16K LDGSTS/step, all CP_WAIT stalls on h, and 14
// of 18 per-step barriers. Only 2 CTA-wide barriers remain (zred reduction).
// ---------------------------------------------------------------------------

#define BATCH   64
#define SEQT    512
#define EMBED   512
#define UNITS   1024
#define GATES   4096
#define BT      (BATCH*SEQT)

#define RT_NCTA    128
#define RT_THREADS 512

// smem layout (bytes):
//   UsB  : 0      .. 131072   (1024x32 tf32 U slice, float2-packed frags)
//   zred : 131072 .. 200704   ([8][64][34] f32 k-warp partials)
//   xzs  : 200704 .. 209920   ([64][36] f32 staged gates)
#define SM_US    0
#define SM_ZR    131072
#define SM_XZ    200704
#define REC_SMEM_BYTES 209920

// ---- device scratch ----
__device__ __align__(16) float g_xz[(size_t)BT * GATES];
__device__ __align__(16) float g_h0[(size_t)BT * UNITS];
__device__ __align__(16) float g_hbuf[2][BATCH * UNITS];
__device__ unsigned g_cnt[8 * 32];   // 8 chunk-group counters, 128B apart

// ---------------------------------------------------------------------------
// helpers
// ---------------------------------------------------------------------------
__device__ __forceinline__ float tf32r(float x) {
    unsigned u;
    asm("cvt.rna.tf32.f32 %0, %1;" : "=r"(u) : "f"(x));
    return __uint_as_float(u);
}

__device__ __forceinline__ float ldcg(const float* p) {
    float v;
    asm volatile("ld.global.cg.f32 %0, [%1];" : "=f"(v) : "l"(p));
    return v;
}

__device__ __forceinline__ void mma_m16n8k8_tf32(float* c, float2 a02, float2 a13, float2 b01) {
    unsigned a0 = __float_as_uint(a02.x), a1 = __float_as_uint(a13.x);
    unsigned a2 = __float_as_uint(a02.y), a3 = __float_as_uint(a13.y);
    unsigned b0 = __float_as_uint(b01.x), b1 = __float_as_uint(b01.y);
    asm volatile(
        "mma.sync.aligned.m16n8k8.row.col.f32.tf32.tf32.f32 "
        "{%0,%1,%2,%3}, {%4,%5,%6,%7}, {%8,%9}, {%0,%1,%2,%3};\n"
        : "+f"(c[0]), "+f"(c[1]), "+f"(c[2]), "+f"(c[3])
        : "r"(a0), "r"(a1), "r"(a2), "r"(a3), "r"(b0), "r"(b1));
}

__device__ __forceinline__ float sigmoidf_(float x) {
    return 1.0f / (1.0f + __expf(-x));
}

#define CP_ASYNC16(dst_u32, src_ptr) \
    asm volatile("cp.async.cg.shared.global [%0], [%1], 16;\n" \
                 :: "r"(dst_u32), "l"(src_ptr))
#define CP_COMMIT() asm volatile("cp.async.commit_group;\n" ::: "memory")
#define CP_WAIT(n)  asm volatile("cp.async.wait_group %0;\n" :: "n"(n) : "memory")

__device__ __forceinline__ void arrive_release(unsigned* p) {
    asm volatile("red.release.gpu.global.add.u32 [%0], %1;\n" :: "l"(p), "r"(1u) : "memory");
}
__device__ __forceinline__ void poll_acquire(const unsigned* p, unsigned target) {
    unsigned v;
    do {
        asm volatile("ld.acquire.gpu.global.u32 %0, [%1];\n" : "=r"(v) : "l"(p) : "memory");
    } while (v < target);
}

// ---------------------------------------------------------------------------
// Big GEMM: C[M=BT x 4096] = Arows[M x K] @ Bmat[K x 4096] + bias
// (unchanged from the passing round-10..13 kernel)
// ---------------------------------------------------------------------------
__global__ __launch_bounds__(256)
void gemm_tf32(const float* __restrict__ A,
               const int*   __restrict__ tokens,
               const float* __restrict__ emb,
               const float* __restrict__ Bmat,
               const float* __restrict__ bias,
               float*       __restrict__ C,
               int K)
{
    __shared__ float2 As[4 * 128 * 4];
    __shared__ float2 Bs[4 * 128 * 4];

    const int tid  = threadIdx.x;
    const int lane = tid & 31;
    const int wid  = tid >> 5;
    const int gid  = lane >> 2;
    const int tig  = lane & 3;

    const int r0 = blockIdx.y * 128;
    const int n0 = blockIdx.x * 128;
    const int wm = wid >> 2;
    const int wn = wid & 3;

    float c[4][4][4];
    #pragma unroll
    for (int i = 0; i < 4; i++)
        #pragma unroll
        for (int j = 0; j < 4; j++)
            #pragma unroll
            for (int k = 0; k < 4; k++) c[i][j][k] = 0.0f;

    for (int k0 = 0; k0 < K; k0 += 32) {
        #pragma unroll 4
        for (int idx = tid; idx < 128 * 32; idx += 256) {
            int row = idx >> 5, kk = idx & 31;
            const float* src = tokens
                ? emb + (size_t)tokens[r0 + row] * EMBED
                : A   + (size_t)(r0 + row) * K;
            float v = tf32r(src[k0 + kk]);
            ((float*)&As[((kk >> 3) * 128 + row) * 4 + (kk & 3)])[(kk >> 2) & 1] = v;
        }
        #pragma unroll 4
        for (int idx = tid; idx < 32 * 128; idx += 256) {
            int kk = idx >> 7, col = idx & 127;
            float v = tf32r(Bmat[(size_t)(k0 + kk) * GATES + n0 + col]);
            ((float*)&Bs[((kk >> 3) * 128 + col) * 4 + (kk & 3)])[(kk >> 2) & 1] = v;
        }
        __syncthreads();

        #pragma unroll
        for (int kc = 0; kc < 4; kc++) {
            float2 a02[4], a13[4];
            #pragma unroll
            for (int mf = 0; mf < 4; mf++) {
                int m = wm * 64 + mf * 16;
                a02[mf] = As[(kc * 128 + m + gid) * 4 + tig];
                a13[mf] = As[(kc * 128 + m + 8 + gid) * 4 + tig];
            }
            #pragma unroll
            for (int nf = 0; nf < 4; nf++) {
                int n = wn * 32 + nf * 8;
                float2 b01 = Bs[(kc * 128 + n + gid) * 4 + tig];
                #pragma unroll
                for (int mf = 0; mf < 4; mf++)
                    mma_m16n8k8_tf32(c[mf][nf], a02[mf], a13[mf], b01);
            }
        }
        __syncthreads();
    }

    #pragma unroll
    for (int mf = 0; mf < 4; mf++) {
        int row = r0 + wm * 64 + mf * 16 + gid;
        #pragma unroll
        for (int nf = 0; nf < 4; nf++) {
            int col = n0 + wn * 32 + nf * 8 + tig * 2;
            float bb0 = bias[col], bb1 = bias[col + 1];
            float2 v0 = make_float2(c[mf][nf][0] + bb0, c[mf][nf][1] + bb1);
            float2 v1 = make_float2(c[mf][nf][2] + bb0, c[mf][nf][3] + bb1);
            *(float2*)&C[(size_t)row * GATES + col]       = v0;
            *(float2*)&C[(size_t)(row + 8) * GATES + col] = v1;
        }
    }
}

// ---------------------------------------------------------------------------
// zero the chunk-group counters (runs before each lstm_rec launch)
// ---------------------------------------------------------------------------
__global__ void zero_cnt() {
    if (threadIdx.x < 8 * 32) g_cnt[threadIdx.x] = 0;
}

// ---------------------------------------------------------------------------
// Persistent recurrent kernel. 128 CTAs x 512 threads, 1 CTA/SM.
// CTA owns units [u0,u0+8) -> 32 gate cols; U slice resident in smem.
// Warp grid: 2 m-warps x 8 k-warps; warp kw owns h cols [kw*128,(kw+1)*128)
// == producer group kw. A-frags read straight from L2 via ld.global.cg.
// Partial z accs (per k-warp) reduced once per step via smem.
// ---------------------------------------------------------------------------
__global__ __launch_bounds__(RT_THREADS, 1)
void lstm_rec(const float* __restrict__ U,    // [1024][4096]
              const float* __restrict__ xz,   // [B][T][4096]
              float*       __restrict__ hall, // [B][T][1024]
              int T)
{
    extern __shared__ char smem_c[];
    float2* UsB  = (float2*)(smem_c + SM_US);
    float*  zred = (float*) (smem_c + SM_ZR);
    float*  xzs  = (float*) (smem_c + SM_XZ);
    const unsigned smem_u32 = (unsigned)__cvta_generic_to_shared(smem_c);

    const int tid  = threadIdx.x;
    const int lane = tid & 31;
    const int wid  = tid >> 5;
    const int gid  = lane >> 2;
    const int tig  = lane & 3;
    const int cta  = blockIdx.x;
    const int u0   = cta * 8;
    const int grp  = cta >> 4;          // this CTA's producer group (units u0/128)

    // one-time: load + tf32-round the CTA's U slice into smem (frag-packed)
    for (int idx = tid; idx < 1024 * 32; idx += RT_THREADS) {
        int k = idx >> 5, cc = idx & 31;
        int G = (cc >> 3) * UNITS + u0 + (cc & 7);
        float v = tf32r(U[(size_t)k * GATES + G]);
        int kcg = k >> 3, kk = k & 7;
        ((float*)&UsB[(kcg * 32 + cc) * 4 + (kk & 3)])[kk >> 2] = v;
    }

    // produce h_0 = 0 for this CTA's slice, then arrive
    {
        int b = tid >> 3, u = tid & 7;       // 512 threads = 64 b x 8 u
        g_hbuf[0][b * UNITS + u0 + u] = 0.0f;
    }
    __syncthreads();
    if (tid == 0) arrive_release(&g_cnt[grp * 32]);

    float creg = 0.0f;                       // cell state, 1 (b,u) pair/thread
    const int ab = tid >> 3, au = tid & 7;   // activation pair

    const int kw = wid & 7;                  // k-warp: h cols [kw*128,(kw+1)*128)
    const int mw = wid >> 3;                 // m-warp: 32 batches
    const int m0 = mw * 32;

    for (int t = 0; t < T; ++t) {
        const float* hcur = g_hbuf[t & 1];
        const unsigned target = 16u * (unsigned)(t + 1);

        // -- stage xz gates for this step (no h dependency; overlaps mma loop)
        {
            int b = tid >> 3, r = tid & 7, g = r >> 1, h4 = r & 1;
            const float* src = xz + ((size_t)(b * T + t)) * GATES + g * UNITS + u0 + h4 * 4;
            unsigned dst = smem_u32 + SM_XZ + (b * 36 + g * 8 + h4 * 4) * 4;
            CP_ASYNC16(dst, src);
            CP_COMMIT();
        }

        // -- per-warp wait: only this warp's producer group must have arrived
        if (lane == 0) poll_acquire(&g_cnt[kw * 32], target);
        __syncwarp();                         // warp-scope ordering for the ld.cg's

        float acc[2][4][4];
        #pragma unroll
        for (int mf = 0; mf < 2; mf++)
            #pragma unroll
            for (int nt = 0; nt < 4; nt++)
                #pragma unroll
                for (int q = 0; q < 4; q++) acc[mf][nt][q] = 0.0f;

        // -- z = h @ Uslice over this warp's 128 k-cols, A-frags from L2
        const float* hb = hcur + kw * 128 + tig;
        #pragma unroll 4
        for (int kc = 0; kc < 16; ++kc) {
            const int k8 = kc * 8;
            float2 a02[2], a13[2];
            #pragma unroll
            for (int mf = 0; mf < 2; ++mf) {
                const float* rp = hb + (m0 + mf * 16 + gid) * UNITS + k8;
                a02[mf] = make_float2(ldcg(rp),           ldcg(rp + 4));
                a13[mf] = make_float2(ldcg(rp + 8 * UNITS), ldcg(rp + 8 * UNITS + 4));
            }
            const int kcg = kw * 16 + kc;
            #pragma unroll
            for (int nt = 0; nt < 4; ++nt) {
                float2 b01 = UsB[(kcg * 32 + nt * 8 + gid) * 4 + tig];
                mma_m16n8k8_tf32(acc[0][nt], a02[0], a13[0], b01);
                mma_m16n8k8_tf32(acc[1][nt], a02[1], a13[1], b01);
            }
        }

        CP_WAIT(0);                           // own xz cp complete (bar makes all visible)

        // -- store per-k-warp partials: zred[kw][row(64)][col(34 pitch)]
        #pragma unroll
        for (int mf = 0; mf < 2; ++mf) {
            int row = m0 + mf * 16 + gid;
            #pragma unroll
            for (int nt = 0; nt < 4; ++nt) {
                int col = nt * 8 + tig * 2;
                *(float2*)&zred[kw * 2176 + row * 34 + col] =
                    make_float2(acc[mf][nt][0], acc[mf][nt][1]);
                *(float2*)&zred[kw * 2176 + (row + 8) * 34 + col] =
                    make_float2(acc[mf][nt][2], acc[mf][nt][3]);
            }
        }
        __syncthreads();

        // -- k-reduction + activations + state update
        {
            float z[4];
            #pragma unroll
            for (int g = 0; g < 4; ++g) {
                float s = 0.0f;
                #pragma unroll
                for (int k = 0; k < 8; ++k)
                    s += zred[k * 2176 + ab * 34 + g * 8 + au];
                z[g] = s + xzs[ab * 36 + g * 8 + au];
            }
            float ig = sigmoidf_(z[0]);
            float fg = sigmoidf_(z[1]);
            float gg = tanhf(z[2]);
            float og = sigmoidf_(z[3]);
            float cx = fg * creg + ig * gg;
            creg = cx;
            float h = og * tanhf(cx);
            hall[((size_t)(ab * T + t)) * UNITS + u0 + au] = h;
            g_hbuf[(t + 1) & 1][ab * UNITS + u0 + au] = tf32r(h);
        }
        __syncthreads();                      // slice writes + xzs/zred reuse safe
        if (tid == 0) arrive_release(&g_cnt[grp * 32]);
    }
}

// ---------------------------------------------------------------------------
// launcher
// ---------------------------------------------------------------------------
extern "C" void kernel_launch(void* const* d_in, const int* in_sizes, int n_in,
                              void* d_out, int out_size)
{
    const int*   tokens = (const int*)  d_in[0];
    const float* emb    = (const float*)d_in[1];
    const float* W0     = (const float*)d_in[2];
    const float* U0     = (const float*)d_in[3];
    const float* b0     = (const float*)d_in[4];
    const float* W1     = (const float*)d_in[5];
    const float* U1     = (const float*)d_in[6];
    const float* b1     = (const float*)d_in[7];
    float* out = (float*)d_out;

    float *xz = nullptr, *h0 = nullptr;
    cudaGetSymbolAddress((void**)&xz, g_xz);
    cudaGetSymbolAddress((void**)&h0, g_h0);

    cudaFuncSetAttribute(lstm_rec, cudaFuncAttributeMaxDynamicSharedMemorySize,
                         REC_SMEM_BYTES);

    dim3 ggrid(GATES / 128, BT / 128);

    // Phase A: xz0 = embed[tokens] @ W0 + b0
    gemm_tf32<<<ggrid, 256>>>(nullptr, tokens, emb, W0, b0, xz, EMBED);
    // Phase B: layer-0 recurrence
    zero_cnt<<<1, 256>>>();
    lstm_rec<<<RT_NCTA, RT_THREADS, REC_SMEM_BYTES>>>(U0, xz, h0, SEQT);
    // Phase C: xz1 = h0 @ W1 + b1
    gemm_tf32<<<ggrid, 256>>>(h0, nullptr, nullptr, W1, b1, xz, UNITS);
    // Phase D: layer-1 recurrence -> output
    zero_cnt<<<1, 256>>>();
    lstm_rec<<<RT_NCTA, RT_THREADS, REC_SMEM_BYTES>>>(U1, xz, out, SEQT);
}

// round 17
// speedup vs baseline: 1.5412x; 1.5412x over previous
#include <cuda_runtime.h>
#include <cuda_bf16.h>
#include <cstdint>

// ---------------------------------------------------------------------------
// TransducerPrediction: embed lookup + 2-layer LSTM (Keras gate order i,f,g,o)
// B=64, T=512, EMBED=512, UNITS=1024, 4U=4096.
//
// Graph (6 nodes):
//   1) gemm_tf32: xz0 = embed[tokens] @ W0 + b0
//   2) zero_cnt
//   3) lstm_rec : layer-0 recurrence -> g_h0
//   4) gemm_tf32: xz1 = g_h0 @ W1 + b1
//   5) zero_cnt
//   6) lstm_rec : layer-1 recurrence -> d_out
//
// R17 = R13 structure (best, 16.2ms) + overhead cuts:
//  - 3-slot h staging pipeline -> ONE __syncthreads per chunk (was 2):
//    cp for chunk c+2 goes to slot (c+2)%3 == (c-1)%3, whose reads finished
//    last iteration, certified by this iteration's barrier.
//  - xz gates prefetched into REGISTERS at step top (4 ld.cg, used only at
//    activation) -> frees 9KB smem for the 3rd slot + removes xz cp group.
//  - fast tanh via __expf on the end-of-step critical path.
// R16's ld.global.cg frag path reverted (8-sector uncoalesced loads).
// ---------------------------------------------------------------------------

#define BATCH   64
#define SEQT    512
#define EMBED   512
#define UNITS   1024
#define GATES   4096
#define BT      (BATCH*SEQT)

#define RT_NCTA    128
#define RT_THREADS 512

// smem layout (bytes):
//   UsB  : 0      .. 131072   (1024x32 tf32 U slice, float2-packed frags)
//   Hs   : 131072 .. 232448   (3 x [64][132] f32 h-chunk slots; overlaid by
//                              zred[8][64][34] f32 partials after last chunk)
#define SM_US    0
#define SM_HS    131072
#define SLOT_B   33792          // 64*132*4 per slot
#define SLOT_F   8448           // floats per slot
#define REC_SMEM_BYTES 232448   // == 227 KB max dynamic smem, exact fit

// ---- device scratch ----
__device__ __align__(16) float g_xz[(size_t)BT * GATES];
__device__ __align__(16) float g_h0[(size_t)BT * UNITS];
__device__ __align__(16) float g_hbuf[2][BATCH * UNITS];
__device__ unsigned g_cnt[8 * 32];   // 8 chunk-group counters, 128B apart

// ---------------------------------------------------------------------------
// helpers
// ---------------------------------------------------------------------------
__device__ __forceinline__ float tf32r(float x) {
    unsigned u;
    asm("cvt.rna.tf32.f32 %0, %1;" : "=r"(u) : "f"(x));
    return __uint_as_float(u);
}

__device__ __forceinline__ float ldcg(const float* p) {
    float v;
    asm volatile("ld.global.cg.f32 %0, [%1];" : "=f"(v) : "l"(p));
    return v;
}

__device__ __forceinline__ void mma_m16n8k8_tf32(float* c, float2 a02, float2 a13, float2 b01) {
    unsigned a0 = __float_as_uint(a02.x), a1 = __float_as_uint(a13.x);
    unsigned a2 = __float_as_uint(a02.y), a3 = __float_as_uint(a13.y);
    unsigned b0 = __float_as_uint(b01.x), b1 = __float_as_uint(b01.y);
    asm volatile(
        "mma.sync.aligned.m16n8k8.row.col.f32.tf32.tf32.f32 "
        "{%0,%1,%2,%3}, {%4,%5,%6,%7}, {%8,%9}, {%0,%1,%2,%3};\n"
        : "+f"(c[0]), "+f"(c[1]), "+f"(c[2]), "+f"(c[3])
        : "r"(a0), "r"(a1), "r"(a2), "r"(a3), "r"(b0), "r"(b1));
}

__device__ __forceinline__ float sigmoidf_(float x) {
    return 1.0f / (1.0f + __expf(-x));
}
__device__ __forceinline__ float tanhf_(float x) {
    // tanh(x) = 1 - 2/(1 + exp(2x)); exact limits at +/-inf via __expf
    return 1.0f - 2.0f / (1.0f + __expf(2.0f * x));
}

#define CP_ASYNC16(dst_u32, src_ptr) \
    asm volatile("cp.async.cg.shared.global [%0], [%1], 16;\n" \
                 :: "r"(dst_u32), "l"(src_ptr))
#define CP_COMMIT() asm volatile("cp.async.commit_group;\n" ::: "memory")
#define CP_WAIT(n)  asm volatile("cp.async.wait_group %0;\n" :: "n"(n) : "memory")

__device__ __forceinline__ void arrive_release(unsigned* p) {
    asm volatile("red.release.gpu.global.add.u32 [%0], %1;\n" :: "l"(p), "r"(1u) : "memory");
}
__device__ __forceinline__ void poll_acquire(const unsigned* p, unsigned target) {
    unsigned v;
    do {
        asm volatile("ld.acquire.gpu.global.u32 %0, [%1];\n" : "=r"(v) : "l"(p) : "memory");
    } while (v < target);
}

// ---------------------------------------------------------------------------
// Big GEMM: C[M=BT x 4096] = Arows[M x K] @ Bmat[K x 4096] + bias
// (unchanged from the passing round-10..13 kernel)
// ---------------------------------------------------------------------------
__global__ __launch_bounds__(256)
void gemm_tf32(const float* __restrict__ A,
               const int*   __restrict__ tokens,
               const float* __restrict__ emb,
               const float* __restrict__ Bmat,
               const float* __restrict__ bias,
               float*       __restrict__ C,
               int K)
{
    __shared__ float2 As[4 * 128 * 4];
    __shared__ float2 Bs[4 * 128 * 4];

    const int tid  = threadIdx.x;
    const int lane = tid & 31;
    const int wid  = tid >> 5;
    const int gid  = lane >> 2;
    const int tig  = lane & 3;

    const int r0 = blockIdx.y * 128;
    const int n0 = blockIdx.x * 128;
    const int wm = wid >> 2;
    const int wn = wid & 3;

    float c[4][4][4];
    #pragma unroll
    for (int i = 0; i < 4; i++)
        #pragma unroll
        for (int j = 0; j < 4; j++)
            #pragma unroll
            for (int k = 0; k < 4; k++) c[i][j][k] = 0.0f;

    for (int k0 = 0; k0 < K; k0 += 32) {
        #pragma unroll 4
        for (int idx = tid; idx < 128 * 32; idx += 256) {
            int row = idx >> 5, kk = idx & 31;
            const float* src = tokens
                ? emb + (size_t)tokens[r0 + row] * EMBED
                : A   + (size_t)(r0 + row) * K;
            float v = tf32r(src[k0 + kk]);
            ((float*)&As[((kk >> 3) * 128 + row) * 4 + (kk & 3)])[(kk >> 2) & 1] = v;
        }
        #pragma unroll 4
        for (int idx = tid; idx < 32 * 128; idx += 256) {
            int kk = idx >> 7, col = idx & 127;
            float v = tf32r(Bmat[(size_t)(k0 + kk) * GATES + n0 + col]);
            ((float*)&Bs[((kk >> 3) * 128 + col) * 4 + (kk & 3)])[(kk >> 2) & 1] = v;
        }
        __syncthreads();

        #pragma unroll
        for (int kc = 0; kc < 4; kc++) {
            float2 a02[4], a13[4];
            #pragma unroll
            for (int mf = 0; mf < 4; mf++) {
                int m = wm * 64 + mf * 16;
                a02[mf] = As[(kc * 128 + m + gid) * 4 + tig];
                a13[mf] = As[(kc * 128 + m + 8 + gid) * 4 + tig];
            }
            #pragma unroll
            for (int nf = 0; nf < 4; nf++) {
                int n = wn * 32 + nf * 8;
                float2 b01 = Bs[(kc * 128 + n + gid) * 4 + tig];
                #pragma unroll
                for (int mf = 0; mf < 4; mf++)
                    mma_m16n8k8_tf32(c[mf][nf], a02[mf], a13[mf], b01);
            }
        }
        __syncthreads();
    }

    #pragma unroll
    for (int mf = 0; mf < 4; mf++) {
        int row = r0 + wm * 64 + mf * 16 + gid;
        #pragma unroll
        for (int nf = 0; nf < 4; nf++) {
            int col = n0 + wn * 32 + nf * 8 + tig * 2;
            float bb0 = bias[col], bb1 = bias[col + 1];
            float2 v0 = make_float2(c[mf][nf][0] + bb0, c[mf][nf][1] + bb1);
            float2 v1 = make_float2(c[mf][nf][2] + bb0, c[mf][nf][3] + bb1);
            *(float2*)&C[(size_t)row * GATES + col]       = v0;
            *(float2*)&C[(size_t)(row + 8) * GATES + col] = v1;
        }
    }
}

// ---------------------------------------------------------------------------
// zero the chunk-group counters (runs before each lstm_rec launch)
// ---------------------------------------------------------------------------
__global__ void zero_cnt() {
    if (threadIdx.x < 8 * 32) g_cnt[threadIdx.x] = 0;
}

// ---------------------------------------------------------------------------
// Persistent recurrent kernel. 128 CTAs x 512 threads, 1 CTA/SM.
// CTA owns units [u0,u0+8) -> 32 gate cols; U slice resident in smem.
// Warp grid: 2 m-warps x 8 k-warps; warp kw does kc pair {2kw,2kw+1}/chunk.
// h staged via cp.async through a 3-slot pipeline (1 bar per chunk).
// Partial z accs (per k-warp) reduced once per step via smem (zred overlays
// the h slots, which are dead by then).
// ---------------------------------------------------------------------------
__global__ __launch_bounds__(RT_THREADS, 1)
void lstm_rec(const float* __restrict__ U,    // [1024][4096]
              const float* __restrict__ xz,   // [B][T][4096]
              float*       __restrict__ hall, // [B][T][1024]
              int T)
{
    extern __shared__ char smem_c[];
    float2* UsB  = (float2*)(smem_c + SM_US);
    float*  Hs   = (float*) (smem_c + SM_HS);
    float*  zred = (float*) (smem_c + SM_HS);   // overlays slots after chunks
    const unsigned smem_u32 = (unsigned)__cvta_generic_to_shared(smem_c);

    const int tid  = threadIdx.x;
    const int lane = tid & 31;
    const int wid  = tid >> 5;
    const int gid  = lane >> 2;
    const int tig  = lane & 3;
    const int cta  = blockIdx.x;
    const int u0   = cta * 8;
    const int grp  = cta >> 4;          // this CTA's producer group (units u0/128)

    // one-time: load + tf32-round the CTA's U slice into smem (frag-packed)
    for (int idx = tid; idx < 1024 * 32; idx += RT_THREADS) {
        int k = idx >> 5, cc = idx & 31;
        int G = (cc >> 3) * UNITS + u0 + (cc & 7);
        float v = tf32r(U[(size_t)k * GATES + G]);
        int kcg = k >> 3, kk = k & 7;
        ((float*)&UsB[(kcg * 32 + cc) * 4 + (kk & 3)])[kk >> 2] = v;
    }

    // produce h_0 = 0 for this CTA's slice, then arrive
    {
        int b = tid >> 3, u = tid & 7;       // 512 threads = 64 b x 8 u
        g_hbuf[0][b * UNITS + u0 + u] = 0.0f;
    }
    __syncthreads();
    if (tid == 0) arrive_release(&g_cnt[grp * 32]);

    float creg = 0.0f;                       // cell state, 1 (b,u) pair/thread
    const int ab = tid >> 3, au = tid & 7;   // activation pair

    const int kw = wid & 7;                  // k-warp: kc pair {2kw,2kw+1}/chunk
    const int mw = wid >> 3;                 // m-warp: 32 batches
    const int m0 = mw * 32;

    for (int t = 0; t < T; ++t) {
        const float* hcur = g_hbuf[t & 1];
        const unsigned target = 16u * (unsigned)(t + 1);

        // -- prefetch this thread's 4 xz gates into registers (used only at
        //    the activation; latency hidden behind the whole chunk loop)
        const size_t xbase = ((size_t)(ab * T + t)) * GATES + u0 + au;
        float xzi = ldcg(xz + xbase);
        float xzf = ldcg(xz + xbase + 1024);
        float xzg = ldcg(xz + xbase + 2048);
        float xzo = ldcg(xz + xbase + 3072);

        // -- single poll point: warp0 lanes 0..7 poll the 8 groups in parallel
        if (wid == 0 && lane < 8) poll_acquire(&g_cnt[lane * 32], target);
        __syncthreads();

        // -- prologue: stage chunks 0,1 into slots 0,1
        #pragma unroll
        for (int pc = 0; pc < 2; ++pc) {
            #pragma unroll
            for (int j = 0; j < 4; ++j) {
                int i = tid + j * RT_THREADS;         // 2048 16B copies
                int row = i >> 5, seg = i & 31;
                unsigned dst = smem_u32 + SM_HS + pc * SLOT_B + row * 528 + seg * 16;
                CP_ASYNC16(dst, hcur + row * UNITS + pc * 128 + seg * 4);
            }
            CP_COMMIT();
        }

        float acc[2][4][4];
        #pragma unroll
        for (int mf = 0; mf < 2; mf++)
            #pragma unroll
            for (int nt = 0; nt < 4; nt++)
                #pragma unroll
                for (int q = 0; q < 4; q++) acc[mf][nt][q] = 0.0f;

        // -- 3-slot pipeline, ONE barrier per chunk:
        //    at iter c: wait chunk c; bar (also certifies reads of chunk c-1
        //    finished on all warps); issue chunk c+2 into slot (c+2)%3 (== the
        //    slot chunk c-1 used); mma on chunk c.
        for (int c = 0; c < 8; ++c) {
            CP_WAIT(1);
            __syncthreads();

            if (c + 2 < 8) {
                int slot = (c + 2) % 3;
                #pragma unroll
                for (int j = 0; j < 4; ++j) {
                    int i = tid + j * RT_THREADS;
                    int row = i >> 5, seg = i & 31;
                    unsigned dst = smem_u32 + SM_HS + slot * SLOT_B + row * 528 + seg * 16;
                    CP_ASYNC16(dst, hcur + row * UNITS + (c + 2) * 128 + seg * 4);
                }
            }
            CP_COMMIT();                      // empty group when c+2>=8 keeps counts aligned

            const float* H = Hs + (c % 3) * SLOT_F;
            #pragma unroll
            for (int j = 0; j < 2; ++j) {
                const int kl = kw * 2 + j;            // local kc in chunk
                const int kcg = c * 16 + kl;
                const float* Hb = H + kl * 8 + tig;
                float2 a02[2], a13[2];
                #pragma unroll
                for (int mf = 0; mf < 2; ++mf) {
                    const float* r0p = Hb + (m0 + mf * 16 + gid) * 132;
                    a02[mf] = make_float2(r0p[0], r0p[4]);
                    a13[mf] = make_float2(r0p[8 * 132], r0p[8 * 132 + 4]);
                }
                #pragma unroll
                for (int nt = 0; nt < 4; ++nt) {
                    float2 b01 = UsB[(kcg * 32 + nt * 8 + gid) * 4 + tig];
                    mma_m16n8k8_tf32(acc[0][nt], a02[0], a13[0], b01);
                    mma_m16n8k8_tf32(acc[1][nt], a02[1], a13[1], b01);
                }
            }
        }

        __syncthreads();                      // all mma reads done -> slots dead

        // -- store per-k-warp partials: zred[kw][row(64)][col(34 pitch)]
        #pragma unroll
        for (int mf = 0; mf < 2; ++mf) {
            int row = m0 + mf * 16 + gid;
            #pragma unroll
            for (int nt = 0; nt < 4; ++nt) {
                int col = nt * 8 + tig * 2;
                *(float2*)&zred[kw * 2176 + row * 34 + col] =
                    make_float2(acc[mf][nt][0], acc[mf][nt][1]);
                *(float2*)&zred[kw * 2176 + (row + 8) * 34 + col] =
                    make_float2(acc[mf][nt][2], acc[mf][nt][3]);
            }
        }
        __syncthreads();

        // -- k-reduction + activations + state update
        {
            float z[4];
            #pragma unroll
            for (int g = 0; g < 4; ++g) {
                float s = 0.0f;
                #pragma unroll
                for (int k = 0; k < 8; ++k)
                    s += zred[k * 2176 + ab * 34 + g * 8 + au];
                z[g] = s;
            }
            float ig = sigmoidf_(z[0] + xzi);
            float fg = sigmoidf_(z[1] + xzf);
            float gg = tanhf_(z[2] + xzg);
            float og = sigmoidf_(z[3] + xzo);
            float cx = fg * creg + ig * gg;
            creg = cx;
            float h = og * tanhf_(cx);
            hall[((size_t)(ab * T + t)) * UNITS + u0 + au] = h;
            g_hbuf[(t + 1) & 1][ab * UNITS + u0 + au] = tf32r(h);
        }
        __syncthreads();                      // slice writes done; smem reusable
        if (tid == 0) arrive_release(&g_cnt[grp * 32]);
    }
}

// ---------------------------------------------------------------------------
// launcher
// ---------------------------------------------------------------------------
extern "C" void kernel_launch(void* const* d_in, const int* in_sizes, int n_in,
                              void* d_out, int out_size)
{
    const int*   tokens = (const int*)  d_in[0];
    const float* emb    = (const float*)d_in[1];
    const float* W0     = (const float*)d_in[2];
    const float* U0     = (const float*)d_in[3];
    const float* b0     = (const float*)d_in[4];
    const float* W1     = (const float*)d_in[5];
    const float* U1     = (const float*)d_in[6];
    const float* b1     = (const float*)d_in[7];
    float* out = (float*)d_out;

    float *xz = nullptr, *h0 = nullptr;
    cudaGetSymbolAddress((void**)&xz, g_xz);
    cudaGetSymbolAddress((void**)&h0, g_h0);

    cudaFuncSetAttribute(lstm_rec, cudaFuncAttributeMaxDynamicSharedMemorySize,
                         REC_SMEM_BYTES);

    dim3 ggrid(GATES / 128, BT / 128);

    // Phase A: xz0 = embed[tokens] @ W0 + b0
    gemm_tf32<<<ggrid, 256>>>(nullptr, tokens, emb, W0, b0, xz, EMBED);
    // Phase B: layer-0 recurrence
    zero_cnt<<<1, 256>>>();
    lstm_rec<<<RT_NCTA, RT_THREADS, REC_SMEM_BYTES>>>(U0, xz, h0, SEQT);
    // Phase C: xz1 = h0 @ W1 + b1
    gemm_tf32<<<ggrid, 256>>>(h0, nullptr, nullptr, W1, b1, xz, UNITS);
    // Phase D: layer-1 recurrence -> output
    zero_cnt<<<1, 256>>>();
    lstm_rec<<<RT_NCTA, RT_THREADS, REC_SMEM_BYTES>>>(U1, xz, out, SEQT);
}